// round 9
// baseline (speedup 1.0000x reference)
#include <cuda_runtime.h>
#include <cstdint>

#define N_NODES 100000
#define N_EDGES 1600000
#define IN_DIM 32
#define OUT_DIM 64
#define N_REL 8
#define K_DIM 256
#define N_SEG (N_NODES * N_REL)      // 800000 segments
#define N_KSTEP 36
#define EPS 1e-10f

static constexpr int NROWTILES = N_NODES / 16;   // 6250
static constexpr int SCAN_BLOCKS = (N_SEG + 1023) / 1024;   // 782

// Scratch (__device__ globals; no allocs)
__device__ float    g_num[(size_t)N_NODES * K_DIM];      // normalized+tf32 update
__device__ uint32_t g_cur[N_SEG];                        // counts -> offsets -> ends
__device__ uint32_t g_bsum[1024];                        // scan block sums
__device__ uint2    g_bin[N_EDGES];                      // (src, w bits) per slot

__device__ __forceinline__ float to_tf32(float v) {
    uint32_t r;
    asm("cvt.rna.tf32.f32 %0, %1;" : "=r"(r) : "f"(v));
    return __uint_as_float(r);
}

// ---------------------------------------------------------------------------
// Pass A: per-segment edge counts
// ---------------------------------------------------------------------------
__global__ void count_kernel(const int* __restrict__ edge_list) {
    const int e = blockIdx.x * blockDim.x + threadIdx.x;
    if (e >= N_EDGES) return;
    const int dst = edge_list[3 * e + 1];
    const int rel = edge_list[3 * e + 2];
    atomicAdd(&g_cur[dst * N_REL + rel], 1u);
}

// ---------------------------------------------------------------------------
// Pass B: exclusive scan of g_cur (3 kernels)
// ---------------------------------------------------------------------------
__global__ void scan1_kernel() {
    __shared__ uint32_t s[1024];
    const int tid = threadIdx.x;
    const int i = blockIdx.x * 1024 + tid;
    const uint32_t v = (i < N_SEG) ? g_cur[i] : 0u;
    s[tid] = v;
    __syncthreads();
#pragma unroll
    for (int off = 1; off < 1024; off <<= 1) {
        const uint32_t t = (tid >= off) ? s[tid - off] : 0u;
        __syncthreads();
        s[tid] += t;
        __syncthreads();
    }
    if (i < N_SEG) g_cur[i] = s[tid] - v;          // exclusive within block
    if (tid == 1023) g_bsum[blockIdx.x] = s[1023]; // block total
}

__global__ void scan2_kernel() {
    __shared__ uint32_t s[1024];
    const int tid = threadIdx.x;
    const uint32_t v = (tid < SCAN_BLOCKS) ? g_bsum[tid] : 0u;
    s[tid] = v;
    __syncthreads();
#pragma unroll
    for (int off = 1; off < 1024; off <<= 1) {
        const uint32_t t = (tid >= off) ? s[tid - off] : 0u;
        __syncthreads();
        s[tid] += t;
        __syncthreads();
    }
    if (tid < SCAN_BLOCKS) g_bsum[tid] = s[tid] - v;  // exclusive block offsets
}

__global__ void scan3_kernel() {
    const int i = blockIdx.x * 1024 + threadIdx.x;
    if (i < N_SEG) g_cur[i] += g_bsum[blockIdx.x];
}

// ---------------------------------------------------------------------------
// Pass C: fill bins. After this, g_cur[seg] = segment END offset.
// ---------------------------------------------------------------------------
__global__ void fill_kernel(const int* __restrict__ edge_list,
                            const float* __restrict__ edge_weight) {
    const int e = blockIdx.x * blockDim.x + threadIdx.x;
    if (e >= N_EDGES) return;
    const int src = edge_list[3 * e + 0];
    const int dst = edge_list[3 * e + 1];
    const int rel = edge_list[3 * e + 2];
    const float w = edge_weight[e];
    const uint32_t pos = atomicAdd(&g_cur[dst * N_REL + rel], 1u);
    g_bin[pos] = make_uint2((uint32_t)src, __float_as_uint(w));
}

// ---------------------------------------------------------------------------
// Pass D: aggregate. 8 lanes per segment; writes g_num once,
//         normalized by 1/(sum_w + eps), tf32-rounded.
// ---------------------------------------------------------------------------
__global__ void aggregate_kernel(const float* __restrict__ x) {
    const int tid  = threadIdx.x;
    const int lane = tid & 31;
    const int sub  = lane >> 3;
    const int i8   = lane & 7;
    const int seg  = ((blockIdx.x * blockDim.x + tid) >> 5) * 4 + sub;
    // grid sized exactly: N_SEG*8/256 blocks, N_SEG%4==0 -> no overflow

    const uint32_t start = (seg == 0) ? 0u : g_cur[seg - 1];
    const uint32_t end   = g_cur[seg];

    float4 acc = make_float4(0.f, 0.f, 0.f, 0.f);
    float  ws  = 0.f;
    for (uint32_t p = start; p < end; p++) {
        const uint2 pr = g_bin[p];
        const float w = __uint_as_float(pr.y);
        const float4 v = reinterpret_cast<const float4*>(
            x + (size_t)pr.x * IN_DIM)[i8];
        acc.x += v.x * w; acc.y += v.y * w;
        acc.z += v.z * w; acc.w += v.w * w;
        ws += w;
    }
    const float inv = __fdividef(1.f, ws + EPS);
    float4 r;
    r.x = to_tf32(acc.x * inv); r.y = to_tf32(acc.y * inv);
    r.z = to_tf32(acc.z * inv); r.w = to_tf32(acc.w * inv);
    reinterpret_cast<float4*>(g_num)[(size_t)seg * 8 + i8] = r;
}

// ---------------------------------------------------------------------------
// GEMM: tf32 MMA, per-warp double-buffered staging, pure LDS.64+MMA path.
// g_num already normalized+rounded; only x block (kb==8) needs cvt at staging.
// ---------------------------------------------------------------------------
#define BF_FLOAT2 (N_KSTEP * 8 * 32)
#define BF_BYTES  (BF_FLOAT2 * 8)                // 73728
#define WROW 40
#define WBUF_FLOATS (16 * WROW)                  // 640
#define WARP_SMEM_FLOATS (2 * WBUF_FLOATS)       // 1280
#define WBUF_OFF  (BF_BYTES + OUT_DIM * 4)
#define SMEM_TOTAL (WBUF_OFF + 16 * WARP_SMEM_FLOATS * 4)   // 155904

__device__ __forceinline__ void mma_tf32(float c[4], uint32_t a0, uint32_t a1,
                                         uint32_t a2, uint32_t a3,
                                         uint32_t b0, uint32_t b1) {
    asm volatile(
        "mma.sync.aligned.m16n8k8.row.col.f32.tf32.tf32.f32 "
        "{%0,%1,%2,%3}, {%4,%5,%6,%7}, {%8,%9}, {%0,%1,%2,%3};"
        : "+f"(c[0]), "+f"(c[1]), "+f"(c[2]), "+f"(c[3])
        : "r"(a0), "r"(a1), "r"(a2), "r"(a3), "r"(b0), "r"(b1));
}

__global__ __launch_bounds__(512, 1)
void gemm_mma_kernel(const float* __restrict__ x,
                     const float* __restrict__ Wl,
                     const float* __restrict__ bl,
                     const float* __restrict__ Ws,
                     const float* __restrict__ bs,
                     float* __restrict__ out) {
    extern __shared__ char smem[];
    float2* sBf   = reinterpret_cast<float2*>(smem);
    float*  sBias = reinterpret_cast<float*>(smem + BF_BYTES);

    const int tid  = threadIdx.x;
    const int wid  = tid >> 5;
    const int lane = tid & 31;
    const int g    = lane >> 2;
    const int tig  = lane & 3;

    float* wbuf0 = reinterpret_cast<float*>(smem + WBUF_OFF) +
                   wid * WARP_SMEM_FLOATS;
    float* wbuf1 = wbuf0 + WBUF_FLOATS;

    const int ldrow = lane >> 3;
    const int ldcol = (lane & 7) * 4;

    // B fragments, k-slot permuted (slot tt <-> k = s*8 + 2*tt)
    for (int idx = tid; idx < BF_FLOAT2; idx += 512) {
        const int l  = idx & 31;
        const int j  = (idx >> 5) & 7;
        const int s  = idx >> 8;
        const int gg = l >> 2, tt = l & 3;
        const int n  = j * 8 + gg;
        const int k0 = s * 8 + 2 * tt;
        const int k1 = k0 + 1;
        const float v0 = (k0 < K_DIM) ? Wl[(size_t)k0 * OUT_DIM + n]
                                      : Ws[(size_t)(k0 - K_DIM) * OUT_DIM + n];
        const float v1 = (k1 < K_DIM) ? Wl[(size_t)k1 * OUT_DIM + n]
                                      : Ws[(size_t)(k1 - K_DIM) * OUT_DIM + n];
        sBf[idx] = make_float2(to_tf32(v0), to_tf32(v1));
    }
    if (tid < OUT_DIM) sBias[tid] = bl[tid] + bs[tid];
    __syncthreads();

    const int nwarps = gridDim.x * 16;

    for (int t = blockIdx.x * 16 + wid; t < NROWTILES; t += nwarps) {
        float acc[8][4];
#pragma unroll
        for (int j = 0; j < 8; j++)
#pragma unroll
            for (int c = 0; c < 4; c++) acc[j][c] = 0.f;

        const float* srcA = g_num + (size_t)t * 16 * K_DIM;
        const float* srcX = x + (size_t)t * 16 * IN_DIM;

        float4 pf[4];
#pragma unroll
        for (int i = 0; i < 4; i++)
            pf[i] = *reinterpret_cast<const float4*>(
                srcA + (size_t)(i * 4 + ldrow) * K_DIM + ldcol);

#pragma unroll
        for (int kb = 0; kb < 9; kb++) {
            float* buf = (kb & 1) ? wbuf1 : wbuf0;

            // stage current block (cvt only for the x block)
            if (kb < 8) {
#pragma unroll
                for (int i = 0; i < 4; i++)
                    *reinterpret_cast<float4*>(
                        buf + (i * 4 + ldrow) * WROW + ldcol) = pf[i];
            } else {
#pragma unroll
                for (int i = 0; i < 4; i++) {
                    float4 v = pf[i];
                    v.x = to_tf32(v.x); v.y = to_tf32(v.y);
                    v.z = to_tf32(v.z); v.w = to_tf32(v.w);
                    *reinterpret_cast<float4*>(
                        buf + (i * 4 + ldrow) * WROW + ldcol) = v;
                }
            }

            // prefetch next block
            if (kb < 7) {
#pragma unroll
                for (int i = 0; i < 4; i++)
                    pf[i] = *reinterpret_cast<const float4*>(
                        srcA + (size_t)(i * 4 + ldrow) * K_DIM + (kb + 1) * 32 + ldcol);
            } else if (kb == 7) {
#pragma unroll
                for (int i = 0; i < 4; i++)
                    pf[i] = *reinterpret_cast<const float4*>(
                        srcX + (size_t)(i * 4 + ldrow) * IN_DIM + ldcol);
            }
            __syncwarp();

            // pure LDS.64 + MMA
#pragma unroll
            for (int ss = 0; ss < 4; ss++) {
                const int fo = ss * 8 + 2 * tig;
                const float2 pA0 = *reinterpret_cast<const float2*>(
                    buf + g * WROW + fo);
                const float2 pA1 = *reinterpret_cast<const float2*>(
                    buf + (g + 8) * WROW + fo);
                const uint32_t a0 = __float_as_uint(pA0.x);
                const uint32_t a2 = __float_as_uint(pA0.y);
                const uint32_t a1 = __float_as_uint(pA1.x);
                const uint32_t a3 = __float_as_uint(pA1.y);
                const float2* bf = sBf + (kb * 4 + ss) * 256 + lane;
#pragma unroll
                for (int j = 0; j < 8; j++) {
                    const float2 bb = bf[j * 32];
                    mma_tf32(acc[j], a0, a1, a2, a3,
                             __float_as_uint(bb.x), __float_as_uint(bb.y));
                }
            }
            __syncwarp();
        }

        const int row0 = t * 16 + g;
        const int row1 = row0 + 8;
#pragma unroll
        for (int j = 0; j < 8; j++) {
            const int col = j * 8 + tig * 2;
            const float b0 = sBias[col], b1 = sBias[col + 1];
            float2 v0 = make_float2(fmaxf(acc[j][0] + b0, 0.f),
                                    fmaxf(acc[j][1] + b1, 0.f));
            float2 v1 = make_float2(fmaxf(acc[j][2] + b0, 0.f),
                                    fmaxf(acc[j][3] + b1, 0.f));
            *reinterpret_cast<float2*>(out + (size_t)row0 * OUT_DIM + col) = v0;
            *reinterpret_cast<float2*>(out + (size_t)row1 * OUT_DIM + col) = v1;
        }
    }
}

// ---------------------------------------------------------------------------
// Launch
// ---------------------------------------------------------------------------
extern "C" void kernel_launch(void* const* d_in, const int* in_sizes, int n_in,
                              void* d_out, int out_size) {
    const float* x     = (const float*)d_in[0];
    const int*   edges = (const int*)  d_in[1];
    const float* ew    = (const float*)d_in[2];
    const float* Wl    = (const float*)d_in[3];
    const float* bl    = (const float*)d_in[4];
    const float* Ws    = (const float*)d_in[5];
    const float* bs    = (const float*)d_in[6];
    float*       out   = (float*)d_out;

    void* pcur = nullptr;
    cudaGetSymbolAddress(&pcur, g_cur);
    cudaMemsetAsync(pcur, 0, N_SEG * sizeof(uint32_t), 0);

    count_kernel<<<(N_EDGES + 255) / 256, 256>>>(edges);
    scan1_kernel<<<SCAN_BLOCKS, 1024>>>();
    scan2_kernel<<<1, 1024>>>();
    scan3_kernel<<<SCAN_BLOCKS, 1024>>>();
    fill_kernel<<<(N_EDGES + 255) / 256, 256>>>(edges, ew);
    aggregate_kernel<<<(N_SEG * 8) / 256, 256>>>(x);

    cudaFuncSetAttribute(gemm_mma_kernel,
                         cudaFuncAttributeMaxDynamicSharedMemorySize,
                         SMEM_TOTAL);
    gemm_mma_kernel<<<148, 512, SMEM_TOTAL>>>(x, Wl, bl, Ws, bs, out);
}

// round 10
// speedup vs baseline: 1.2484x; 1.2484x over previous
#include <cuda_runtime.h>
#include <cstdint>

#define N_NODES 100000
#define N_EDGES 1600000
#define IN_DIM 32
#define OUT_DIM 64
#define N_REL 8
#define K_DIM 256
#define N_KSTEP 36
#define EPS 1e-10f

static constexpr int NROWTILES = N_NODES / 16;   // 6250 exact

// Scratch (alloc-free rule): row-major — edge writes stay 128B-contiguous.
__device__ float g_num[(size_t)N_NODES * K_DIM];
__device__ float g_den[(size_t)N_NODES * N_REL];

__device__ __forceinline__ float to_tf32(float v) {
    uint32_t r;
    asm("cvt.rna.tf32.f32 %0, %1;" : "=r"(r) : "f"(v));
    return __uint_as_float(r);
}
__device__ __forceinline__ uint32_t smem_u32(const void* p) {
    uint32_t a;
    asm("{ .reg .u64 t; cvta.to.shared.u64 t, %1; cvt.u32.u64 %0, t; }"
        : "=r"(a) : "l"(p));
    return a;
}
#define CP_ASYNC16(smem_addr, gptr) \
    asm volatile("cp.async.cg.shared.global [%0], [%1], 16;" \
                 :: "r"(smem_addr), "l"(gptr))
#define CP_COMMIT() asm volatile("cp.async.commit_group;")

// ---------------------------------------------------------------------------
// Kernel 1: edge scatter, 8 lanes per edge (R6 best — unchanged).
// ---------------------------------------------------------------------------
__global__ void scatter_kernel(const int* __restrict__ edge_list,
                               const float* __restrict__ edge_weight,
                               const float* __restrict__ x) {
    const int tid   = threadIdx.x;
    const int gwarp = (blockIdx.x * blockDim.x + tid) >> 5;
    const int lane  = tid & 31;
    const int sub   = lane >> 3;
    const int i8    = lane & 7;

    const int e0 = gwarp * 4;

    int   ev = 0;
    float wv = 0.f;
    if (lane < 12)      ev = edge_list[(size_t)e0 * 3 + lane];
    else if (lane < 16) wv = edge_weight[e0 + (lane - 12)];

    const int   src = __shfl_sync(0xffffffffu, ev, sub * 3 + 0);
    const int   dst = __shfl_sync(0xffffffffu, ev, sub * 3 + 1);
    const int   rel = __shfl_sync(0xffffffffu, ev, sub * 3 + 2);
    const float w   = __shfl_sync(0xffffffffu, wv, 12 + sub);

    const float4 v =
        reinterpret_cast<const float4*>(x + (size_t)src * IN_DIM)[i8];
    float* basep = g_num + (size_t)dst * K_DIM + rel * IN_DIM + i8 * 4;

    asm volatile(
        "red.global.add.v4.f32 [%0], {%1, %2, %3, %4};"
        :: "l"(basep),
           "f"(v.x * w), "f"(v.y * w), "f"(v.z * w), "f"(v.w * w)
        : "memory");

    if (i8 == 0)
        atomicAdd(g_den + (size_t)dst * N_REL + rel, w);
}

// ---------------------------------------------------------------------------
// Kernel 2: tf32 MMA GEMM, cp.async 3-stage per-warp ring staging.
//   Consumer path identical to R7 best (scalar LDS + dinv + cvt + MMA).
// ---------------------------------------------------------------------------
#define BF_FLOAT2 (N_KSTEP * 8 * 32)
#define BF_BYTES  (BF_FLOAT2 * 8)                 // 73728
#define WROW 36                                    // floats per staged row
#define WBUF_FLOATS (16 * WROW)                    // 576 per stage
#define N_STAGE 3
#define WARP_SMEM_FLOATS (N_STAGE * WBUF_FLOATS)   // 1728
#define WBUF_OFF  (BF_BYTES + OUT_DIM * 4)         // 73984
#define SMEM_TOTAL (WBUF_OFF + 16 * WARP_SMEM_FLOATS * 4)   // 184576

__device__ __forceinline__ void mma_tf32(float c[4], uint32_t a0, uint32_t a1,
                                         uint32_t a2, uint32_t a3,
                                         uint32_t b0, uint32_t b1) {
    asm volatile(
        "mma.sync.aligned.m16n8k8.row.col.f32.tf32.tf32.f32 "
        "{%0,%1,%2,%3}, {%4,%5,%6,%7}, {%8,%9}, {%0,%1,%2,%3};"
        : "+f"(c[0]), "+f"(c[1]), "+f"(c[2]), "+f"(c[3])
        : "r"(a0), "r"(a1), "r"(a2), "r"(a3), "r"(b0), "r"(b1));
}

__global__ __launch_bounds__(512, 1)
void gemm_mma_kernel(const float* __restrict__ x,
                     const float* __restrict__ Wl,
                     const float* __restrict__ bl,
                     const float* __restrict__ Ws,
                     const float* __restrict__ bs,
                     float* __restrict__ out) {
    extern __shared__ char smem[];
    float2* sBf   = reinterpret_cast<float2*>(smem);
    float*  sBias = reinterpret_cast<float*>(smem + BF_BYTES);

    const int tid  = threadIdx.x;
    const int wid  = tid >> 5;
    const int lane = tid & 31;
    const int g    = lane >> 2;
    const int tig  = lane & 3;

    float* wbuf = reinterpret_cast<float*>(smem + WBUF_OFF) +
                  wid * WARP_SMEM_FLOATS;
    const uint32_t wbuf_a = smem_u32(wbuf);

    const int ldrow = lane >> 3;          // 0..3
    const int ldcol = (lane & 7) * 4;     // float offset

    // per-lane cp.async dest byte offsets within a stage (4 chunks)
    uint32_t dsto[4];
#pragma unroll
    for (int i = 0; i < 4; i++)
        dsto[i] = ((i * 4 + ldrow) * WROW + ldcol) * 4;

    // ---- stage B fragments once (R7 layout: slot tt <-> k = s*8+tt) ----
    for (int idx = tid; idx < BF_FLOAT2; idx += 512) {
        const int l  = idx & 31;
        const int j  = (idx >> 5) & 7;
        const int s  = idx >> 8;
        const int gg = l >> 2, tt = l & 3;
        const int n  = j * 8 + gg;
        const int k0 = s * 8 + tt;
        const int k1 = k0 + 4;
        const float v0 = (k0 < K_DIM) ? Wl[(size_t)k0 * OUT_DIM + n]
                                      : Ws[(size_t)(k0 - K_DIM) * OUT_DIM + n];
        const float v1 = (k1 < K_DIM) ? Wl[(size_t)k1 * OUT_DIM + n]
                                      : Ws[(size_t)(k1 - K_DIM) * OUT_DIM + n];
        sBf[idx] = make_float2(to_tf32(v0), to_tf32(v1));
    }
    if (tid < OUT_DIM) sBias[tid] = bl[tid] + bs[tid];
    __syncthreads();

    const int nwarps = gridDim.x * 16;

    for (int t = blockIdx.x * 16 + wid; t < NROWTILES; t += nwarps) {
        const float* srcA = g_num + (size_t)t * 16 * K_DIM;
        const float* srcX = x + (size_t)t * 16 * IN_DIM;

        // issue a k-block's 4 cp.async chunks into stage (kb % 3)
        auto issue = [&](int kb) {
            const uint32_t sb = wbuf_a + (kb % N_STAGE) * (WBUF_FLOATS * 4);
            if (kb < 8) {
#pragma unroll
                for (int i = 0; i < 4; i++)
                    CP_ASYNC16(sb + dsto[i],
                               srcA + (size_t)(i * 4 + ldrow) * K_DIM +
                                   kb * 32 + ldcol);
            } else {
#pragma unroll
                for (int i = 0; i < 4; i++)
                    CP_ASYNC16(sb + dsto[i],
                               srcX + (size_t)(i * 4 + ldrow) * IN_DIM + ldcol);
            }
            CP_COMMIT();
        };

        issue(0);
        issue(1);

        // ---- 1/den in registers (R7) ----
        float dinv0[8], dinv1[8];
        {
            const int row0 = t * 16 + g;
            const float4* d0 = reinterpret_cast<const float4*>(g_den + (size_t)row0 * N_REL);
            const float4* d1 = reinterpret_cast<const float4*>(g_den + (size_t)(row0 + 8) * N_REL);
            float4 a = d0[0], b = d0[1], c = d1[0], d = d1[1];
            dinv0[0] = __fdividef(1.f, a.x + EPS); dinv0[1] = __fdividef(1.f, a.y + EPS);
            dinv0[2] = __fdividef(1.f, a.z + EPS); dinv0[3] = __fdividef(1.f, a.w + EPS);
            dinv0[4] = __fdividef(1.f, b.x + EPS); dinv0[5] = __fdividef(1.f, b.y + EPS);
            dinv0[6] = __fdividef(1.f, b.z + EPS); dinv0[7] = __fdividef(1.f, b.w + EPS);
            dinv1[0] = __fdividef(1.f, c.x + EPS); dinv1[1] = __fdividef(1.f, c.y + EPS);
            dinv1[2] = __fdividef(1.f, c.z + EPS); dinv1[3] = __fdividef(1.f, c.w + EPS);
            dinv1[4] = __fdividef(1.f, d.x + EPS); dinv1[5] = __fdividef(1.f, d.y + EPS);
            dinv1[6] = __fdividef(1.f, d.z + EPS); dinv1[7] = __fdividef(1.f, d.w + EPS);
        }

        float acc[8][4];
#pragma unroll
        for (int j = 0; j < 8; j++)
#pragma unroll
            for (int c = 0; c < 4; c++) acc[j][c] = 0.f;

#pragma unroll
        for (int kb = 0; kb < 9; kb++) {
            // wait for stage kb; keep 1 group in flight except at the tail
            if (kb < 7)
                asm volatile("cp.async.wait_group 1;" ::: "memory");
            else
                asm volatile("cp.async.wait_group 0;" ::: "memory");
            __syncwarp();

            if (kb < 7) issue(kb + 2);

            float* buf = wbuf + (kb % N_STAGE) * WBUF_FLOATS;
            const float d0 = (kb < 8) ? dinv0[kb] : 1.f;
            const float d1 = (kb < 8) ? dinv1[kb] : 1.f;

#pragma unroll
            for (int ss = 0; ss < 4; ss++) {
                const int kl = ss * 8 + tig;
                const float f0 = buf[g * WROW + kl];
                const float f2 = buf[g * WROW + kl + 4];
                const float f1 = buf[(g + 8) * WROW + kl];
                const float f3 = buf[(g + 8) * WROW + kl + 4];
                const uint32_t a0 = __float_as_uint(to_tf32(f0 * d0));
                const uint32_t a2 = __float_as_uint(to_tf32(f2 * d0));
                const uint32_t a1 = __float_as_uint(to_tf32(f1 * d1));
                const uint32_t a3 = __float_as_uint(to_tf32(f3 * d1));
                const float2* bf = sBf + (kb * 4 + ss) * 256 + lane;
#pragma unroll
                for (int j = 0; j < 8; j++) {
                    const float2 bb = bf[j * 32];
                    mma_tf32(acc[j], a0, a1, a2, a3,
                             __float_as_uint(bb.x), __float_as_uint(bb.y));
                }
            }
            __syncwarp();   // all lanes done reading before stage reuse
        }

        // ---- epilogue ----
        const int row0 = t * 16 + g;
        const int row1 = row0 + 8;
#pragma unroll
        for (int j = 0; j < 8; j++) {
            const int col = j * 8 + tig * 2;
            const float b0 = sBias[col], b1 = sBias[col + 1];
            float2 v0 = make_float2(fmaxf(acc[j][0] + b0, 0.f),
                                    fmaxf(acc[j][1] + b1, 0.f));
            float2 v1 = make_float2(fmaxf(acc[j][2] + b0, 0.f),
                                    fmaxf(acc[j][3] + b1, 0.f));
            *reinterpret_cast<float2*>(out + (size_t)row0 * OUT_DIM + col) = v0;
            *reinterpret_cast<float2*>(out + (size_t)row1 * OUT_DIM + col) = v1;
        }
    }
}

// ---------------------------------------------------------------------------
// Launch
// ---------------------------------------------------------------------------
extern "C" void kernel_launch(void* const* d_in, const int* in_sizes, int n_in,
                              void* d_out, int out_size) {
    const float* x     = (const float*)d_in[0];
    const int*   edges = (const int*)  d_in[1];
    const float* ew    = (const float*)d_in[2];
    const float* Wl    = (const float*)d_in[3];
    const float* bl    = (const float*)d_in[4];
    const float* Ws    = (const float*)d_in[5];
    const float* bs    = (const float*)d_in[6];
    float*       out   = (float*)d_out;

    void* pnum = nullptr; void* pden = nullptr;
    cudaGetSymbolAddress(&pnum, g_num);
    cudaGetSymbolAddress(&pden, g_den);
    cudaMemsetAsync(pnum, 0, (size_t)N_NODES * K_DIM * sizeof(float), 0);
    cudaMemsetAsync(pden, 0, (size_t)N_NODES * N_REL * sizeof(float), 0);

    scatter_kernel<<<(N_EDGES * 8) / 256, 256>>>(edges, ew, x);

    cudaFuncSetAttribute(gemm_mma_kernel,
                         cudaFuncAttributeMaxDynamicSharedMemorySize,
                         SMEM_TOTAL);
    gemm_mma_kernel<<<148, 512, SMEM_TOTAL>>>(x, Wl, bl, Ws, bs, out);
}